// round 15
// baseline (speedup 1.0000x reference)
#include <cuda_runtime.h>
#include <cuda_bf16.h>
#include <cstdint>
#include <cstddef>

// Problem constants (confirmed)
#define B_   64
#define N_   256
#define I_   256
#define F_   512
#define NSG  230

#define XN   4194304ull            // B*N*I
#define WN   8388608ull            // B*I*F
#define IFSZ 131072ull             // I*F

// bf16 scratch  X: 0=xrh 1=xrl 2=xih 3=xil   W: 0=wrh 1=wrl 2=-wih 3=-wil
__device__ __nv_bfloat16 g_XS[16777216];   // 4*XN
__device__ __nv_bfloat16 g_WS[33554432];   // 4*WN

// ---------------- helpers ----------------
__device__ __forceinline__ uint32_t smem_u32(const void* p) {
    uint32_t a;
    asm("{ .reg .u64 t; cvta.to.shared.u64 t, %1; cvt.u32.u64 %0, t; }"
        : "=r"(a) : "l"(p));
    return a;
}
__device__ __forceinline__ uint32_t pack_bf2(__nv_bfloat16 a, __nv_bfloat16 b) {
    return (uint32_t)__bfloat16_as_ushort(a) |
           ((uint32_t)__bfloat16_as_ushort(b) << 16);
}
__device__ __forceinline__ void split4(float4 v, uint2& hi, uint2& lo) {
    __nv_bfloat16 h0 = __float2bfloat16(v.x), h1 = __float2bfloat16(v.y);
    __nv_bfloat16 h2 = __float2bfloat16(v.z), h3 = __float2bfloat16(v.w);
    __nv_bfloat16 l0 = __float2bfloat16(v.x - __bfloat162float(h0));
    __nv_bfloat16 l1 = __float2bfloat16(v.y - __bfloat162float(h1));
    __nv_bfloat16 l2 = __float2bfloat16(v.z - __bfloat162float(h2));
    __nv_bfloat16 l3 = __float2bfloat16(v.w - __bfloat162float(h3));
    hi.x = pack_bf2(h0, h1); hi.y = pack_bf2(h2, h3);
    lo.x = pack_bf2(l0, l1); lo.y = pack_bf2(l2, l3);
}
__device__ __forceinline__ void ldsm4(uint32_t* r, uint32_t addr) {
    asm volatile("ldmatrix.sync.aligned.m8n8.x4.shared.b16 {%0,%1,%2,%3}, [%4];"
                 : "=r"(r[0]), "=r"(r[1]), "=r"(r[2]), "=r"(r[3]) : "r"(addr));
}
__device__ __forceinline__ void ldsm4t(uint32_t* r, uint32_t addr) {
    asm volatile("ldmatrix.sync.aligned.m8n8.x4.trans.shared.b16 {%0,%1,%2,%3}, [%4];"
                 : "=r"(r[0]), "=r"(r[1]), "=r"(r[2]), "=r"(r[3]) : "r"(addr));
}
__device__ __forceinline__ void mma16816(float* d, const uint32_t* a,
                                         const uint32_t* b) {
    asm volatile(
        "mma.sync.aligned.m16n8k16.row.col.f32.bf16.bf16.f32 "
        "{%0,%1,%2,%3}, {%4,%5,%6,%7}, {%8,%9}, {%0,%1,%2,%3};"
        : "+f"(d[0]), "+f"(d[1]), "+f"(d[2]), "+f"(d[3])
        : "r"(a[0]), "r"(a[1]), "r"(a[2]), "r"(a[3]), "r"(b[0]), "r"(b[1]));
}
__device__ __forceinline__ void cp16(uint32_t dst, const void* src) {
    asm volatile("cp.async.cg.shared.global [%0], [%1], 16;"
                 :: "r"(dst), "l"(src) : "memory");
}
__device__ __forceinline__ void cp_commit() {
    asm volatile("cp.async.commit_group;" ::: "memory");
}

// ---------------- kernel 1: split x ----------------
__global__ __launch_bounds__(256) void k_split_x(const float* __restrict__ xr,
                                                 const float* __restrict__ xi) {
    size_t g = (size_t)blockIdx.x * 256 + threadIdx.x;
    if (g >= XN / 4) return;
    uint2 hi, lo;
    split4(((const float4*)xr)[g], hi, lo);
    ((uint2*)(g_XS + 0 * XN))[g] = hi;
    ((uint2*)(g_XS + 1 * XN))[g] = lo;
    split4(((const float4*)xi)[g], hi, lo);
    ((uint2*)(g_XS + 2 * XN))[g] = hi;
    ((uint2*)(g_XS + 3 * XN))[g] = lo;
}

// ---------------- kernel 2: gather + split weights ----------------
__global__ __launch_bounds__(256) void k_split_w(const float* __restrict__ wr,
                                                 const float* __restrict__ wi,
                                                 const int* __restrict__ sgv) {
    __shared__ int s_sg;
    const int b = blockIdx.y;
    if (threadIdx.x == 0) {
        int odd = 0;
        for (int i = 1; i < B_; i += 2) odd |= sgv[i];
        int v = (odd == 0) ? sgv[2 * b] : sgv[b];
        if (v < 0) v = 0;
        if (v >= NSG) v = NSG - 1;
        s_sg = v;
    }
    __syncthreads();
    const size_t base = (size_t)s_sg * IFSZ;
    size_t g = (size_t)blockIdx.x * 256 + threadIdx.x;
    if (g >= IFSZ / 4) return;
    const size_t dstq = b * (IFSZ / 4) + g;
    uint2 hi, lo;
    split4(((const float4*)(wr + base))[g], hi, lo);
    ((uint2*)(g_WS + 0 * WN))[dstq] = hi;
    ((uint2*)(g_WS + 1 * WN))[dstq] = lo;
    float4 v = ((const float4*)(wi + base))[g];
    v.x = -v.x; v.y = -v.y; v.z = -v.z; v.w = -v.w;
    split4(v, hi, lo);
    ((uint2*)(g_WS + 2 * WN))[dstq] = hi;
    ((uint2*)(g_WS + 3 * WN))[dstq] = lo;
}

// ---------------- kernel 3: pipelined bf16 HMMA GEMM ----------------
// tile 128m x 128f, K chunks of 16, 2-stage cp.async double buffer.
// 8 warps = 4(m) x 2(n); warp tile 32m x 64f.
// smem/stage: A 4 tensors [128][48B pad] = 24576 ; B 4 tensors [16][272B pad] = 17408
#define SA_T   6144
#define SA_SZ  24576
#define SB_T   4352
#define STAGE  41984           // 24576 + 17408
#define SMEM_SZ (2 * STAGE)    // 83968

__global__ __launch_bounds__(256, 2) void sg_mma_kernel(
    const int* __restrict__ sgv, const float* __restrict__ brl,
    float* __restrict__ out)
{
    extern __shared__ char smem[];
    const uint32_t sbm = smem_u32(smem);

    const int tid = threadIdx.x;
    const int wid = tid >> 5, lid = tid & 31;
    const int bb = blockIdx.z;
    const int n0 = blockIdx.y * 128;
    const int f0 = blockIdx.x * 128;
    const int wm = wid & 3, wn = wid >> 2;

    __shared__ int s_sg;
    if (tid == 0) {
        int odd = 0;
        for (int i = 1; i < B_; i += 2) odd |= sgv[i];
        int v = (odd == 0) ? sgv[2 * bb] : sgv[bb];
        if (v < 0) v = 0;
        if (v >= NSG) v = NSG - 1;
        s_sg = v;
    }

    // per-thread static load indices (8 cp.async per stage)
    // A: 1024 chunks: t=idx>>8, m=(idx&255)>>1, ch=idx&1
    // B: 1024 chunks: t=idx>>8, k=(idx&255)>>4, sg16=idx&15
    const size_t xbase = ((size_t)bb * N_ + n0) * I_;
    const size_t wbase = (size_t)bb * IFSZ + f0;

    auto issue_stage = [&](int it, int buf) {
        const int i0 = it * 16;
        const uint32_t st = sbm + buf * STAGE;
#pragma unroll
        for (int q = 0; q < 4; q++) {
            const int idx = tid + q * 256;
            const int t = idx >> 8, rem = idx & 255;
            const int m = rem >> 1, ch = rem & 1;
            cp16(st + t * SA_T + m * 48 + ch * 16,
                 g_XS + (size_t)t * XN + xbase + (size_t)m * I_ + i0 + ch * 8);
        }
#pragma unroll
        for (int q = 0; q < 4; q++) {
            const int idx = tid + q * 256;
            const int t = idx >> 8, rem = idx & 255;
            const int k = rem >> 4, s16 = rem & 15;
            cp16(st + SA_SZ + t * SB_T + k * 272 + s16 * 16,
                 g_WS + (size_t)t * WN + wbase + (size_t)(i0 + k) * F_ + s16 * 8);
        }
        cp_commit();
    };

    float acc[2][8][4];
#pragma unroll
    for (int mi = 0; mi < 2; mi++)
#pragma unroll
        for (int nb = 0; nb < 8; nb++)
#pragma unroll
            for (int q = 0; q < 4; q++) acc[mi][nb][q] = 0.0f;

    issue_stage(0, 0);
    issue_stage(1, 1);

    const int rowL = lid & 15;
    const int halfL = lid >> 4;

    for (int it = 0; it < 16; it++) {
        if (it < 15)
            asm volatile("cp.async.wait_group 1;" ::: "memory");
        else
            asm volatile("cp.async.wait_group 0;" ::: "memory");
        __syncthreads();

        const uint32_t st = sbm + (it & 1) * STAGE;
#pragma unroll
        for (int g = 0; g < 4; g++) {
            uint32_t a[2][4];
#pragma unroll
            for (int mi = 0; mi < 2; mi++)
                ldsm4(a[mi], st + g * SA_T +
                              (wm * 32 + mi * 16 + rowL) * 48 + halfL * 16);
            const int nB = (g == 0 || g == 2) ? 2 : 1;
#pragma unroll
            for (int e = 0; e < 2; e++) {
                if (e >= nB) break;
                const int tb = (g < 2) ? e : 2 + e;
#pragma unroll
                for (int nh = 0; nh < 4; nh++) {
                    uint32_t r[4];
                    ldsm4t(r, st + SA_SZ + tb * SB_T + rowL * 272 +
                              (wn * 64 + nh * 16) * 2 + halfL * 16);
#pragma unroll
                    for (int mi = 0; mi < 2; mi++) {
                        mma16816(acc[mi][nh * 2 + 0], a[mi], r);
                        mma16816(acc[mi][nh * 2 + 1], a[mi], r + 2);
                    }
                }
            }
        }
        __syncthreads();
        if (it + 2 < 16) issue_stage(it + 2, it & 1);
    }

    // ---- epilogue: bias + direct float2 stores ----
    const int r = lid >> 2, c = (lid & 3) * 2;
    const float* bias = brl + (size_t)s_sg * F_;
#pragma unroll
    for (int mi = 0; mi < 2; mi++)
#pragma unroll
        for (int nb = 0; nb < 8; nb++) {
            const int f = f0 + wn * 64 + nb * 8 + c;
            const int m = n0 + wm * 32 + mi * 16 + r;
            const float b0 = bias[f], b1 = bias[f + 1];
            *(float2*)(out + ((size_t)bb * N_ + m) * F_ + f) =
                make_float2(acc[mi][nb][0] + b0, acc[mi][nb][1] + b1);
            *(float2*)(out + ((size_t)bb * N_ + m + 8) * F_ + f) =
                make_float2(acc[mi][nb][2] + b0, acc[mi][nb][3] + b1);
        }
}

// ---------------- safe fallback ----------------
__global__ void fallback_zero_kernel(unsigned char* out, size_t nbytes) {
    size_t i = (size_t)blockIdx.x * blockDim.x + threadIdx.x;
    size_t stride = (size_t)gridDim.x * blockDim.x;
    for (; i < nbytes; i += stride) out[i] = 0;
}

extern "C" void kernel_launch(void* const* d_in, const int* in_sizes, int n_in,
                              void* d_out, int out_size) {
    const long long SZ_IN = (long long)B_ * N_ * I_;
    const long long SZ_W  = (long long)NSG * I_ * F_;
    const long long SZ_B  = (long long)NSG * F_;

    bool ok = (n_in == 7) &&
              in_sizes[0] == SZ_IN && in_sizes[1] == SZ_IN &&
              in_sizes[3] == SZ_W  && in_sizes[4] == SZ_W  &&
              in_sizes[5] == SZ_B  && in_sizes[6] == SZ_B;
    if (!ok) {
        fallback_zero_kernel<<<512, 256>>>((unsigned char*)d_out,
                                           (size_t)(out_size > 0 ? out_size : 0));
        return;
    }

    const float* xr  = (const float*)d_in[0];
    const float* xi  = (const float*)d_in[1];
    const int*   sgp = (const int*)d_in[2];
    const float* wr  = (const float*)d_in[3];
    const float* wi  = (const float*)d_in[4];
    const float* brl = (const float*)d_in[5];

    k_split_x<<<(unsigned)(XN / 4 / 256), 256>>>(xr, xi);
    k_split_w<<<dim3((unsigned)(IFSZ / 4 / 256), B_), 256>>>(wr, wi, sgp);

    cudaFuncSetAttribute(sg_mma_kernel,
                         cudaFuncAttributeMaxDynamicSharedMemorySize, SMEM_SZ);
    dim3 grid(F_ / 128, N_ / 128, B_);    // 4 x 2 x 64 = 512 blocks
    sg_mma_kernel<<<grid, 256, SMEM_SZ>>>(sgp, brl, (float*)d_out);
}